// round 4
// baseline (speedup 1.0000x reference)
#include <cuda_runtime.h>
#include <math.h>

// Shapes fixed by reference: [2,4,32,64,64]
constexpr int Cc   = 32;           // channels
constexpr int HW   = 4096;         // 64*64 positions
constexpr int NI   = 8;            // B*L items
constexpr int BPI  = 64;           // blocks per item
constexpr int TP   = 64;           // positions per block tile
constexpr int PITCH = 66;          // even (8B LDS.64 rows), not mult of 4
constexpr int TH1  = 384;          // 6 groups x 64 threads (3 mats x 2 pos-halves)

// Scratch: [item][block][mat(A,B,M)][32*32]
__device__ float g_scr1[(size_t)NI * BPI * 3 * 1024];
__device__ float g_part[192];

// smem carve: sS[32][66] | sT[32][66] | invS[64] | invT[64]; stage reuses front.
constexpr int SM_SS   = 0;
constexpr int SM_ST   = Cc * PITCH;          // 2112
constexpr int SM_INVS = 2 * Cc * PITCH;      // 4224
constexpr int SM_INVT = SM_INVS + TP;        // 4288
constexpr int SM_TOT  = SM_INVT + TP;        // 4352 floats = 17408 B

__global__ __launch_bounds__(TH1, 3) void k_partial(const float* __restrict__ S,
                                                    const float* __restrict__ T) {
    __shared__ __align__(16) float smem_f[SM_TOT];
    float* sS   = smem_f + SM_SS;    // [c*PITCH + p]
    float* sT   = smem_f + SM_ST;
    float* invS = smem_f + SM_INVS;
    float* invT = smem_f + SM_INVT;

    const int n   = blockIdx.y;
    const int blk = blockIdx.x;
    const int tid = threadIdx.x;
    const int p0  = blk * TP;

    const float2* __restrict__ Sb2 = (const float2*)(S + (size_t)n * Cc * HW);
    const float2* __restrict__ Tb2 = (const float2*)(T + (size_t)n * Cc * HW);

    // ---- Load tile [32 x 64] as float2 (coalesced) ----
    for (int v = tid; v < Cc * (TP / 2); v += TH1) {
        const int c = v >> 5;          // channel
        const int q = v & 31;          // float2 index within row
        const float2 a = Sb2[(size_t)c * (HW / 2) + (p0 >> 1) + q];
        const float2 b = Tb2[(size_t)c * (HW / 2) + (p0 >> 1) + q];
        *(float2*)&sS[c * PITCH + 2 * q] = a;
        *(float2*)&sT[c * PITCH + 2 * q] = b;
    }
    __syncthreads();

    // ---- Per-position inverse norms ----
    if (tid < TP) {
        float s = 0.f;
#pragma unroll
        for (int c = 0; c < Cc; ++c) { const float v = sS[c * PITCH + tid]; s = fmaf(v, v, s); }
        invS[tid] = 1.f / (sqrtf(s) + 1e-8f);
    } else if (tid < 2 * TP) {
        const int p = tid - TP;
        float s = 0.f;
#pragma unroll
        for (int c = 0; c < Cc; ++c) { const float v = sT[c * PITCH + p]; s = fmaf(v, v, s); }
        invT[p] = 1.f / (sqrtf(s) + 1e-8f);
    }
    __syncthreads();

    // ---- Normalize in place (float2) ----
    for (int v = tid; v < Cc * (TP / 2); v += TH1) {
        const int c = v >> 5;
        const int q = v & 31;
        const float2 is = *(const float2*)&invS[2 * q];
        const float2 it = *(const float2*)&invT[2 * q];
        float2 a = *(float2*)&sS[c * PITCH + 2 * q];
        float2 b = *(float2*)&sT[c * PITCH + 2 * q];
        a.x *= is.x; a.y *= is.y;
        b.x *= it.x; b.y *= it.y;
        *(float2*)&sS[c * PITCH + 2 * q] = a;
        *(float2*)&sT[c * PITCH + 2 * q] = b;
    }
    __syncthreads();

    // ---- Rank-2 accumulation (f32x2 over adjacent positions) ----
    // group = tid>>6 in 0..5: mat = group%3 (0:A=T.T^t, 1:B=S.S^t, 2:M=S.T^t),
    // ph = group/3 selects position half (0: p in [0,32), 1: p in [32,64)).
    const int grpAll = tid >> 6;
    const int ph   = (grpAll >= 3) ? 1 : 0;
    const int mat  = grpAll - 3 * ph;
    const int lt   = tid & 63;
    const int i0   = (lt >> 3) << 2;   // 0,4,...,28
    const int j0   = (lt & 7) << 2;    // 0,4,...,28

    const float* Xi = (mat == 0) ? sT : sS;
    const float* Xj = (mat == 1) ? sS : sT;
    const int pA = ph * 32, pB = pA + 32;

    unsigned long long acc2[16];
#pragma unroll
    for (int k = 0; k < 16; ++k) acc2[k] = 0ull;

#pragma unroll 4
    for (int p = pA; p < pB; p += 2) {
        unsigned long long xi2[4], xj2[4];
#pragma unroll
        for (int r = 0; r < 4; ++r)
            xi2[r] = *(const unsigned long long*)&Xi[(i0 + r) * PITCH + p];
#pragma unroll
        for (int q = 0; q < 4; ++q)
            xj2[q] = *(const unsigned long long*)&Xj[(j0 + q) * PITCH + p];
#pragma unroll
        for (int r = 0; r < 4; ++r)
#pragma unroll
            for (int q = 0; q < 4; ++q)
                asm("fma.rn.f32x2 %0, %1, %2, %0;"
                    : "+l"(acc2[r * 4 + q])
                    : "l"(xi2[r]), "l"(xj2[q]));
    }
    __syncthreads();   // all tile reads done; smem front is reusable as staging

    // ---- Combine the two position-halves, write partials ----
    float* stage = smem_f;   // [mat][32][32] = 3072 floats (fits in tile area)
    if (ph == 1) {
#pragma unroll
        for (int r = 0; r < 4; ++r) {
            float4 v4;
            const float2 a0 = *(const float2*)&acc2[r * 4 + 0];
            const float2 a1 = *(const float2*)&acc2[r * 4 + 1];
            const float2 a2 = *(const float2*)&acc2[r * 4 + 2];
            const float2 a3 = *(const float2*)&acc2[r * 4 + 3];
            v4.x = a0.x + a0.y; v4.y = a1.x + a1.y;
            v4.z = a2.x + a2.y; v4.w = a3.x + a3.y;
            *(float4*)&stage[mat * 1024 + (i0 + r) * 32 + j0] = v4;
        }
    }
    __syncthreads();
    if (ph == 0) {
        float* out = g_scr1 + (((size_t)n * BPI + blk) * 3 + mat) * 1024;
#pragma unroll
        for (int r = 0; r < 4; ++r) {
            const float4 s4 = *(const float4*)&stage[mat * 1024 + (i0 + r) * 32 + j0];
            const float2 a0 = *(const float2*)&acc2[r * 4 + 0];
            const float2 a1 = *(const float2*)&acc2[r * 4 + 1];
            const float2 a2 = *(const float2*)&acc2[r * 4 + 2];
            const float2 a3 = *(const float2*)&acc2[r * 4 + 3];
            float4 v4;
            v4.x = a0.x + a0.y + s4.x; v4.y = a1.x + a1.y + s4.y;
            v4.z = a2.x + a2.y + s4.z; v4.w = a3.x + a3.y + s4.w;
            *(float4*)&out[(i0 + r) * 32 + j0] = v4;
        }
    }
}

// 192 blocks: (item n, mat, slice s of 128 elements). 256 threads: two halves
// of the 64-block range summed in parallel, combined, squared, weighted, reduced.
__global__ __launch_bounds__(256) void k_reduce1() {
    const int bid = blockIdx.x;
    const int n   = bid / 24;
    const int rem = bid % 24;
    const int mat = rem >> 3;
    const int s   = rem & 7;
    const int t   = threadIdx.x;
    const int bsel = t >> 7;            // 0: blocks 0..31, 1: 32..63
    const int tl   = t & 127;
    const int e    = s * 128 + tl;

    float v = 0.f;
    const size_t base = ((size_t)n * BPI) * 3 + mat;
#pragma unroll 8
    for (int b = bsel * 32; b < bsel * 32 + 32; ++b)
        v += g_scr1[(base + (size_t)b * 3) * 1024 + e];

    __shared__ float red[256];
    red[t] = v;
    __syncthreads();
    if (t < 128) {
        const float tot = red[t] + red[t + 128];
        red[t] = (mat == 2) ? -2.f * tot * tot : tot * tot;
    }
    __syncthreads();
    for (int off = 64; off > 0; off >>= 1) {
        if (t < off) red[t] += red[t + off];
        __syncthreads();
    }
    if (t == 0) g_part[bid] = red[0];
}

__global__ __launch_bounds__(256) void k_reduce2(float* __restrict__ out) {
    const int t = threadIdx.x;
    __shared__ float red[256];
    red[t] = (t < 192) ? g_part[t] : 0.f;
    __syncthreads();
    for (int off = 128; off > 0; off >>= 1) {
        if (t < off) red[t] += red[t + off];
        __syncthreads();
    }
    // loss = total / (HW^2) / (B*L)
    if (t == 0) out[0] = red[0] * (1.f / (16777216.f * 8.f));
}

extern "C" void kernel_launch(void* const* d_in, const int* in_sizes, int n_in,
                              void* d_out, int out_size) {
    const float* S = (const float*)d_in[0];
    const float* T = (const float*)d_in[1];
    (void)in_sizes; (void)n_in; (void)out_size;

    dim3 g1(BPI, NI);
    k_partial<<<g1, TH1>>>(S, T);
    k_reduce1<<<192, 256>>>();
    k_reduce2<<<1, 256>>>((float*)d_out);
}

// round 5
// speedup vs baseline: 1.2968x; 1.2968x over previous
#include <cuda_runtime.h>
#include <math.h>

// Shapes fixed by reference: [2,4,32,64,64]
constexpr int Cc    = 32;          // channels
constexpr int HW    = 4096;        // 64*64 positions
constexpr int NI    = 8;           // B*L items
constexpr int BPI   = 64;          // blocks per item
constexpr int TP    = 64;          // positions per block tile
constexpr int PITCH = 68;          // 17 x 16B: LDS.128-aligned rows, odd quad-bank stride
constexpr int TH1   = 192;         // 3 groups x 64 threads (one per Gram matrix)

// Scratch: [item][block][mat(A,B,M)][32*32]
__device__ float g_scr1[(size_t)NI * BPI * 3 * 1024];
__device__ float g_part[96];

// Physical row for logical channel c: spreads 4-strided and 8-strided row sets
// across all 8 quad-banks (conflict-free LDS.128 in the main loop).
__device__ __forceinline__ int rowmap(int c) { return ((c & 3) << 3) | (c >> 2); }

__global__ __launch_bounds__(TH1) void k_partial(const float* __restrict__ S,
                                                 const float* __restrict__ T) {
    __shared__ __align__(16) float sS[Cc * PITCH];
    __shared__ __align__(16) float sT[Cc * PITCH];
    __shared__ __align__(16) float invS[TP];
    __shared__ __align__(16) float invT[TP];

    const int n   = blockIdx.y;
    const int blk = blockIdx.x;
    const int tid = threadIdx.x;
    const int p0  = blk * TP;

    const float4* __restrict__ Sb4 = (const float4*)(S + (size_t)n * Cc * HW);
    const float4* __restrict__ Tb4 = (const float4*)(T + (size_t)n * Cc * HW);

    // ---- Load tile [32 x 64] as float4, rows permuted by rowmap ----
    for (int v = tid; v < Cc * (TP / 4); v += TH1) {
        const int c = v >> 4;          // logical channel
        const int q = v & 15;          // float4 index within row
        const int pr = rowmap(c);
        const float4 a = Sb4[(size_t)c * (HW / 4) + (p0 >> 2) + q];
        const float4 b = Tb4[(size_t)c * (HW / 4) + (p0 >> 2) + q];
        *(float4*)&sS[pr * PITCH + 4 * q] = a;
        *(float4*)&sT[pr * PITCH + 4 * q] = b;
    }
    __syncthreads();

    // ---- Per-position inverse norms (row set = all rows; permutation-invariant) ----
    if (tid < TP) {
        float s = 0.f;
#pragma unroll
        for (int r = 0; r < Cc; ++r) { const float v = sS[r * PITCH + tid]; s = fmaf(v, v, s); }
        invS[tid] = 1.f / (sqrtf(s) + 1e-8f);
    } else if (tid < 2 * TP) {
        const int p = tid - TP;
        float s = 0.f;
#pragma unroll
        for (int r = 0; r < Cc; ++r) { const float v = sT[r * PITCH + p]; s = fmaf(v, v, s); }
        invT[p] = 1.f / (sqrtf(s) + 1e-8f);
    }
    __syncthreads();

    // ---- Normalize in place (float4; per-position scale, row-agnostic) ----
    for (int v = tid; v < Cc * (TP / 4); v += TH1) {
        const int r = v >> 4;          // physical row directly
        const int q = v & 15;
        const float4 is = *(const float4*)&invS[4 * q];
        const float4 it = *(const float4*)&invT[4 * q];
        float4 a = *(float4*)&sS[r * PITCH + 4 * q];
        float4 b = *(float4*)&sT[r * PITCH + 4 * q];
        a.x *= is.x; a.y *= is.y; a.z *= is.z; a.w *= is.w;
        b.x *= it.x; b.y *= it.y; b.z *= it.z; b.w *= it.w;
        *(float4*)&sS[r * PITCH + 4 * q] = a;
        *(float4*)&sT[r * PITCH + 4 * q] = b;
    }
    __syncthreads();

    // ---- Gram accumulation ----
    // group = tid>>6: 0 -> A (T.T^t), 1 -> B (S.S^t), 2 -> M (S.T^t)
    // Thread patch: logical rows {4*ii + rr}, cols {4*jj + qq}; physical rows
    // 8*rr + ii (xi) and 8*qq + jj (xj) -> conflict-free LDS.128.
    const int grp = tid >> 6;
    const int lt  = tid & 63;
    const int ii  = lt >> 3;           // 0..7
    const int jj  = lt & 7;            // 0..7

    const float* __restrict__ Xi = (grp == 0) ? sT : sS;
    const float* __restrict__ Xj = (grp == 1) ? sS : sT;
    const float* xiB = Xi + ii * PITCH;   // + (8*rr)*PITCH + p  (immediates)
    const float* xjB = Xj + jj * PITCH;   // + (8*qq)*PITCH + p

    unsigned long long acc2[16];
#pragma unroll
    for (int k = 0; k < 16; ++k) acc2[k] = 0ull;

#pragma unroll
    for (int p = 0; p < TP; p += 4) {
        float4 xi4[4], xj4[4];
#pragma unroll
        for (int rr = 0; rr < 4; ++rr) xi4[rr] = *(const float4*)&xiB[(8 * rr) * PITCH + p];
#pragma unroll
        for (int qq = 0; qq < 4; ++qq) xj4[qq] = *(const float4*)&xjB[(8 * qq) * PITCH + p];
#pragma unroll
        for (int rr = 0; rr < 4; ++rr) {
            const unsigned long long xiL = *(const unsigned long long*)&xi4[rr].x;
            const unsigned long long xiH = *(const unsigned long long*)&xi4[rr].z;
#pragma unroll
            for (int qq = 0; qq < 4; ++qq) {
                const unsigned long long xjL = *(const unsigned long long*)&xj4[qq].x;
                const unsigned long long xjH = *(const unsigned long long*)&xj4[qq].z;
                asm("fma.rn.f32x2 %0, %1, %2, %0;"
                    : "+l"(acc2[rr * 4 + qq]) : "l"(xiL), "l"(xjL));
                asm("fma.rn.f32x2 %0, %1, %2, %0;"
                    : "+l"(acc2[rr * 4 + qq]) : "l"(xiH), "l"(xjH));
            }
        }
    }

    // ---- Write partials (logical indices) ----
    float* out = g_scr1 + (((size_t)n * BPI + blk) * 3 + grp) * 1024;
#pragma unroll
    for (int rr = 0; rr < 4; ++rr) {
        float4 v4;
        const float2 a0 = *(const float2*)&acc2[rr * 4 + 0];
        const float2 a1 = *(const float2*)&acc2[rr * 4 + 1];
        const float2 a2 = *(const float2*)&acc2[rr * 4 + 2];
        const float2 a3 = *(const float2*)&acc2[rr * 4 + 3];
        v4.x = a0.x + a0.y; v4.y = a1.x + a1.y;
        v4.z = a2.x + a2.y; v4.w = a3.x + a3.y;
        *(float4*)&out[(4 * ii + rr) * 32 + 4 * jj] = v4;
    }
}

// 96 blocks x 256 threads: one thread per Gram element (8 items x 3 mats x 1024).
// Sum the 64 block-partials, square, weight (-2 for M), block-reduce.
__global__ __launch_bounds__(256) void k_reduce1() {
    const int gid = blockIdx.x * 256 + threadIdx.x;   // 0..24575
    const int n   = gid / 3072;
    const int rem = gid % 3072;                       // mat*1024 + el
    const int mat = rem >> 10;
    const int t   = threadIdx.x;

    float v = 0.f;
#pragma unroll 8
    for (int b = 0; b < BPI; ++b)
        v += g_scr1[((size_t)(n * BPI + b)) * 3072 + rem];
    float contrib = (mat == 2) ? -2.f * v * v : v * v;

    __shared__ float red[256];
    red[t] = contrib;
    __syncthreads();
    for (int off = 128; off > 0; off >>= 1) {
        if (t < off) red[t] += red[t + off];
        __syncthreads();
    }
    if (t == 0) g_part[blockIdx.x] = red[0];
}

__global__ __launch_bounds__(128) void k_reduce2(float* __restrict__ out) {
    const int t = threadIdx.x;
    __shared__ float red[128];
    red[t] = (t < 96) ? g_part[t] : 0.f;
    __syncthreads();
    for (int off = 64; off > 0; off >>= 1) {
        if (t < off) red[t] += red[t + off];
        __syncthreads();
    }
    // loss = total / (HW^2) / (B*L)
    if (t == 0) out[0] = red[0] * (1.f / (16777216.f * 8.f));
}

extern "C" void kernel_launch(void* const* d_in, const int* in_sizes, int n_in,
                              void* d_out, int out_size) {
    const float* S = (const float*)d_in[0];
    const float* T = (const float*)d_in[1];
    (void)in_sizes; (void)n_in; (void)out_size;

    dim3 g1(BPI, NI);
    k_partial<<<g1, TH1>>>(S, T);
    k_reduce1<<<96, 256>>>();
    k_reduce2<<<1, 128>>>((float*)d_out);
}